// round 3
// baseline (speedup 1.0000x reference)
#include <cuda_runtime.h>
#include <math.h>
#include <float.h>

#define BB 8
#define NN 4096
#define KK 9
#define NPTS (BB*NN)        // 32768
#define NROWS (NPTS*KK)     // 294912
#define TPB1 128
#define NBLK1 (NPTS/TPB1)   // 256
#define SMEM1 (NN*16 + 512) // pts float4 + W1/b1

// Scratch (no cudaMalloc allowed)
__device__ float g_h1[NROWS*10];     // 11.25 MB
__device__ float g_part1[NBLK1*20];
__device__ float g_bn1[20];          // scale[10], shift[10]
__device__ float g_mm[NPTS*20];      // max[10], min[10] of h2 per point
__device__ float g_part2[NBLK1*20];
__device__ float g_bn2[20];

// ---------------------------------------------------------------------------
// K1: kNN + geometric features + linear1, per-block partial BN stats
// ---------------------------------------------------------------------------
__global__ void __launch_bounds__(TPB1) k1_knn_feat(
    const float* __restrict__ x, const float* __restrict__ W1,
    const float* __restrict__ b1)
{
    extern __shared__ unsigned char sraw[];
    float4* sp = (float4*)sraw;                       // pts + x2, 64KB
    float*  w1s = (float*)(sraw + (size_t)NN * 16);   // 100
    float*  b1s = w1s + 100;                          // 10

    const int tid = threadIdx.x;
    const int b  = blockIdx.x / (NN / TPB1);
    const int nb = blockIdx.x % (NN / TPB1);

    const float* xb = x + (size_t)b * NN * 3;
    for (int m = tid; m < NN; m += TPB1) {
        float px = xb[m*3+0], py = xb[m*3+1], pz = xb[m*3+2];
        sp[m] = make_float4(px, py, pz, px*px + py*py + pz*pz);
    }
    if (tid < 100) w1s[tid] = W1[tid];
    if (tid < 10)  b1s[tid] = b1[tid];
    __syncthreads();

    const int n = nb * TPB1 + tid;
    const float4 q = sp[n];
    const float qx = q.x, qy = q.y, qz = q.z, q2 = q.w;

    // top-10 smallest D, ties -> lower index (strict < under increasing scan)
    float bd[10]; int bi[10];
    #pragma unroll
    for (int t = 0; t < 10; t++) { bd[t] = FLT_MAX; bi[t] = 0; }

    #pragma unroll 4
    for (int m = 0; m < NN; m++) {
        float4 c = sp[m];                       // uniform addr -> LDS broadcast
        float dot = qx*c.x + qy*c.y + qz*c.z;
        float d = (q2 + c.w) - 2.0f * dot;      // matches ref formula
        if (d < bd[9]) {                        // rare path
            bd[9] = d; bi[9] = m;
            #pragma unroll
            for (int t = 9; t > 0; t--) {
                if (bd[t] < bd[t-1]) {
                    float td = bd[t]; bd[t] = bd[t-1]; bd[t-1] = td;
                    int   ti = bi[t]; bi[t] = bi[t-1]; bi[t-1] = ti;
                }
            }
        }
    }

    // neighbors 1..9 (drop nearest = self), relative vectors + angle
    float rx[9], ry[9], rz[9], ph[9];
    #pragma unroll
    for (int j = 0; j < 9; j++) {
        float4 c = sp[bi[j+1]];
        rx[j] = c.x - qx; ry[j] = c.y - qy; rz[j] = c.z - qz;
        ph[j] = atan2f(ry[j], rx[j]);
    }
    // stable insertion sort of phi
    int ord[9];
    #pragma unroll
    for (int j = 0; j < 9; j++) ord[j] = j;
    for (int i = 1; i < 9; i++) {
        int o = ord[i]; float p = ph[o]; int t = i - 1;
        while (t >= 0 && ph[ord[t]] > p) { ord[t+1] = ord[t]; t--; }
        ord[t+1] = o;
    }

    float s[10], ss[10];
    #pragma unroll
    for (int ch = 0; ch < 10; ch++) { s[ch] = 0.f; ss[ch] = 0.f; }

    const int point = b * NN + n;
    float* outrow = g_h1 + (size_t)point * 90;
    float mask = 0.f;

    #pragma unroll 1
    for (int j = 0; j < 9; j++) {
        int a = ord[j], e = ord[(j + 1) % 9];
        float ax = rx[a], ay = ry[a], az = rz[a];
        float ex = rx[e], ey = ry[e], ez = rz[e];
        float cx = 0.5f*(ax+ex), cy = 0.5f*(ay+ey), cz = 0.5f*(az+ez);
        float nx = ay*ez - az*ey;
        float ny = az*ex - ax*ez;
        float nz = ax*ey - ay*ex;
        float nrm = sqrtf(nx*nx + ny*ny + nz*nz);
        float inv = 1.0f / (nrm + 1e-6f);
        nx *= inv; ny *= inv; nz *= inv;
        if (j == 0) mask = (nx > 0.f) ? 1.f : -1.f;
        nx *= mask; ny *= mask; nz *= mask;
        float pos = (nx*cx + ny*cy + nz*cz) * 0.57735026918962576f; // /sqrt(3)
        float dt = ax*ex + ay*ey + az*ez;
        float nA = sqrtf(ax*ax + ay*ay + az*az);
        float nB = sqrtf(ex*ex + ey*ey + ez*ez);
        float ct = dt / (nA*nB + 1e-8f);
        ct = fminf(1.f, fmaxf(-1.f, ct));
        float ang = acosf(ct);
        float feat[10] = {cx, cy, cz, nx, ny, nz, pos, ang, nA, nB};
        #pragma unroll
        for (int ch = 0; ch < 10; ch++) {
            float h = b1s[ch];
            #pragma unroll
            for (int f = 0; f < 10; f++) h = fmaf(feat[f], w1s[ch*10+f], h);
            outrow[j*10 + ch] = h;
            s[ch] += h; ss[ch] += h * h;
        }
    }

    // deterministic block reduction of stats
    __syncthreads();  // done reading sp; reuse as reduction buffer
    float* red = (float*)sraw;
    #pragma unroll
    for (int off = 16; off; off >>= 1) {
        #pragma unroll
        for (int ch = 0; ch < 10; ch++) {
            s[ch]  += __shfl_down_sync(0xffffffffu, s[ch],  off);
            ss[ch] += __shfl_down_sync(0xffffffffu, ss[ch], off);
        }
    }
    int wid = tid >> 5, lid = tid & 31;
    if (lid == 0) {
        #pragma unroll
        for (int ch = 0; ch < 10; ch++) {
            red[wid*20 + ch]      = s[ch];
            red[wid*20 + 10 + ch] = ss[ch];
        }
    }
    __syncthreads();
    if (tid < 20) {
        float v = red[tid] + red[20+tid] + red[40+tid] + red[60+tid];
        g_part1[blockIdx.x*20 + tid] = v;
    }
}

// ---------------------------------------------------------------------------
// K2/K4: finalize BN stats -> scale/shift
// ---------------------------------------------------------------------------
__global__ void kreduce(int which, const float* __restrict__ g,
                        const float* __restrict__ be)
{
    __shared__ float red[20];
    const float* part = which ? g_part2 : g_part1;
    float* bn = which ? g_bn2 : g_bn1;
    int t = threadIdx.x;
    if (t < 20) {
        float v = 0.f;
        for (int i = 0; i < NBLK1; i++) v += part[i*20 + t];
        red[t] = v;
    }
    __syncthreads();
    if (t < 10) {
        const float inv_n = 1.0f / (float)NROWS;
        float mean = red[t] * inv_n;
        float var  = red[10+t] * inv_n - mean * mean;
        float sc = g[t] * rsqrtf(var + 1e-5f);
        bn[t]      = sc;
        bn[10 + t] = be[t] - mean * sc;
    }
}

// ---------------------------------------------------------------------------
// K3: bn1+relu -> linear2; per-point max/min of h2; partial BN2 stats
// ---------------------------------------------------------------------------
__global__ void __launch_bounds__(TPB1) k3_layer2(
    const float* __restrict__ W2, const float* __restrict__ b2)
{
    __shared__ float w2s[100], b2s[10], sc1[10], sh1[10];
    __shared__ float red[80];
    int tid = threadIdx.x;
    if (tid < 100) w2s[tid] = W2[tid];
    if (tid < 10) {
        b2s[tid] = b2[tid];
        sc1[tid] = g_bn1[tid];
        sh1[tid] = g_bn1[10 + tid];
    }
    __syncthreads();

    int point = blockIdx.x * TPB1 + tid;
    const float* row = g_h1 + (size_t)point * 90;

    float mx[10], mn[10], s[10], ss[10];
    #pragma unroll
    for (int ch = 0; ch < 10; ch++) {
        mx[ch] = -FLT_MAX; mn[ch] = FLT_MAX; s[ch] = 0.f; ss[ch] = 0.f;
    }
    #pragma unroll 1
    for (int j = 0; j < 9; j++) {
        float t1[10];
        #pragma unroll
        for (int ch = 0; ch < 10; ch++) {
            float h = fmaf(row[j*10 + ch], sc1[ch], sh1[ch]);
            t1[ch] = fmaxf(h, 0.f);
        }
        #pragma unroll
        for (int ch = 0; ch < 10; ch++) {
            float h2 = b2s[ch];
            #pragma unroll
            for (int f = 0; f < 10; f++) h2 = fmaf(t1[f], w2s[ch*10+f], h2);
            mx[ch] = fmaxf(mx[ch], h2);
            mn[ch] = fminf(mn[ch], h2);
            s[ch] += h2; ss[ch] += h2 * h2;
        }
    }
    #pragma unroll
    for (int ch = 0; ch < 10; ch++) {
        g_mm[(size_t)point*20 + ch]      = mx[ch];
        g_mm[(size_t)point*20 + 10 + ch] = mn[ch];
    }

    #pragma unroll
    for (int off = 16; off; off >>= 1) {
        #pragma unroll
        for (int ch = 0; ch < 10; ch++) {
            s[ch]  += __shfl_down_sync(0xffffffffu, s[ch],  off);
            ss[ch] += __shfl_down_sync(0xffffffffu, ss[ch], off);
        }
    }
    int wid = tid >> 5, lid = tid & 31;
    if (lid == 0) {
        #pragma unroll
        for (int ch = 0; ch < 10; ch++) {
            red[wid*20 + ch]      = s[ch];
            red[wid*20 + 10 + ch] = ss[ch];
        }
    }
    __syncthreads();
    if (tid < 20) {
        float v = red[tid] + red[20+tid] + red[40+tid] + red[60+tid];
        g_part2[blockIdx.x*20 + tid] = v;
    }
}

// ---------------------------------------------------------------------------
// K5: out = max_k relu(bn2(h2)) via monotonicity: pick max (a>=0) or min (a<0)
// ---------------------------------------------------------------------------
__global__ void k5_final(float* __restrict__ out)
{
    int i = blockIdx.x * 256 + threadIdx.x;
    if (i >= NPTS * 10) return;
    int point = i / 10, ch = i - point * 10;
    float a = g_bn2[ch], sh = g_bn2[10 + ch];
    float h = (a >= 0.f) ? g_mm[(size_t)point*20 + ch]
                         : g_mm[(size_t)point*20 + 10 + ch];
    out[i] = fmaxf(fmaf(a, h, sh), 0.f);
}

// ---------------------------------------------------------------------------
extern "C" void kernel_launch(void* const* d_in, const int* in_sizes, int n_in,
                              void* d_out, int out_size)
{
    const float* x   = (const float*)d_in[0];
    const float* W1  = (const float*)d_in[1];
    const float* b1  = (const float*)d_in[2];
    const float* g1  = (const float*)d_in[3];
    const float* be1 = (const float*)d_in[4];
    const float* W2  = (const float*)d_in[5];
    const float* b2  = (const float*)d_in[6];
    const float* g2  = (const float*)d_in[7];
    const float* be2 = (const float*)d_in[8];
    float* out = (float*)d_out;

    cudaFuncSetAttribute(k1_knn_feat,
                         cudaFuncAttributeMaxDynamicSharedMemorySize, SMEM1);

    k1_knn_feat<<<NBLK1, TPB1, SMEM1>>>(x, W1, b1);
    kreduce<<<1, 32>>>(0, g1, be1);
    k3_layer2<<<NBLK1, TPB1>>>(W2, b2);
    kreduce<<<1, 32>>>(1, g2, be2);
    k5_final<<<(NPTS*10 + 255)/256, 256>>>(out);
}

// round 8
// speedup vs baseline: 1.1272x; 1.1272x over previous
#include <cuda_runtime.h>
#include <math.h>
#include <float.h>

#define BB 8
#define NN 4096
#define KK 9
#define NPTS (BB*NN)        // 32768
#define NROWS (NPTS*KK)     // 294912
#define TPB1 128
#define NBLK1 (NPTS/TPB1)   // 256
#define SMEM1 (NN*16 + 512) // pts float4 + W1/b1

// Scratch (no cudaMalloc allowed). g_h1 is channel-major: [(j*10+ch)*NPTS + point]
__device__ float g_h1[NROWS*10];     // 11.25 MB
__device__ float g_part1[NBLK1*20];
__device__ float g_bn1[20];          // scale[10], shift[10]
__device__ float g_mm[NPTS*20];      // max[10], min[10] of h2 per point
__device__ float g_part2[NBLK1*20];
__device__ float g_bn2[20];

// ---------------------------------------------------------------------------
// K1: kNN + geometric features + linear1, per-block partial BN stats
// ---------------------------------------------------------------------------
__global__ void __launch_bounds__(TPB1) k1_knn_feat(
    const float* __restrict__ x, const float* __restrict__ W1,
    const float* __restrict__ b1)
{
    extern __shared__ unsigned char sraw[];
    float4* sp = (float4*)sraw;                       // pts + x2, 64KB
    float*  w1s = (float*)(sraw + (size_t)NN * 16);   // 100
    float*  b1s = w1s + 100;                          // 10

    const int tid = threadIdx.x;
    const int b  = blockIdx.x / (NN / TPB1);
    const int nb = blockIdx.x % (NN / TPB1);

    const float* xb = x + (size_t)b * NN * 3;
    for (int m = tid; m < NN; m += TPB1) {
        float px = xb[m*3+0], py = xb[m*3+1], pz = xb[m*3+2];
        sp[m] = make_float4(px, py, pz, px*px + py*py + pz*pz);
    }
    if (tid < 100) w1s[tid] = W1[tid];
    if (tid < 10)  b1s[tid] = b1[tid];
    __syncthreads();

    const int n = nb * TPB1 + tid;
    const float4 q = sp[n];
    const float qx = q.x, qy = q.y, qz = q.z, q2 = q.w;

    // top-10 smallest D, ties -> lower index (strict < under increasing scan)
    float bd[10]; int bi[10];
    #pragma unroll
    for (int t = 0; t < 10; t++) { bd[t] = FLT_MAX; bi[t] = 0; }

    #pragma unroll 8
    for (int m = 0; m < NN; m++) {
        float4 c = sp[m];                       // uniform addr -> LDS broadcast
        float dot = qx*c.x + qy*c.y + qz*c.z;
        float d = (q2 + c.w) - 2.0f * dot;      // matches ref formula
        bool ins = d < bd[9];
        // warp-uniform branch: no BSSY/BSYNC divergence penalty
        if (__ballot_sync(0xffffffffu, ins)) {
            // non-inserting lanes re-insert their own tail element: exact no-op
            bd[9] = ins ? d : bd[9];
            bi[9] = ins ? m : bi[9];
            #pragma unroll
            for (int t = 9; t > 0; t--) {
                bool sw = bd[t] < bd[t-1];
                float fa = bd[t], fb = bd[t-1];
                bd[t]   = sw ? fb : fa;
                bd[t-1] = sw ? fa : fb;
                int ia = bi[t], ib = bi[t-1];
                bi[t]   = sw ? ib : ia;
                bi[t-1] = sw ? ia : ib;
            }
        }
    }

    // neighbors 1..9 (drop nearest = self), relative vectors + angle
    float rx[9], ry[9], rz[9], ph[9];
    #pragma unroll
    for (int j = 0; j < 9; j++) {
        float4 c = sp[bi[j+1]];
        rx[j] = c.x - qx; ry[j] = c.y - qy; rz[j] = c.z - qz;
        ph[j] = atan2f(ry[j], rx[j]);
    }
    // stable insertion sort of phi
    int ord[9];
    #pragma unroll
    for (int j = 0; j < 9; j++) ord[j] = j;
    for (int i = 1; i < 9; i++) {
        int o = ord[i]; float p = ph[o]; int t = i - 1;
        while (t >= 0 && ph[ord[t]] > p) { ord[t+1] = ord[t]; t--; }
        ord[t+1] = o;
    }

    float s[10], ss[10];
    #pragma unroll
    for (int ch = 0; ch < 10; ch++) { s[ch] = 0.f; ss[ch] = 0.f; }

    const int point = b * NN + n;
    float mask = 0.f;

    #pragma unroll 1
    for (int j = 0; j < 9; j++) {
        int a = ord[j], e = ord[(j + 1) % 9];
        float ax = rx[a], ay = ry[a], az = rz[a];
        float ex = rx[e], ey = ry[e], ez = rz[e];
        float cx = 0.5f*(ax+ex), cy = 0.5f*(ay+ey), cz = 0.5f*(az+ez);
        float nx = ay*ez - az*ey;
        float ny = az*ex - ax*ez;
        float nz = ax*ey - ay*ex;
        float nrm = sqrtf(nx*nx + ny*ny + nz*nz);
        float inv = 1.0f / (nrm + 1e-6f);
        nx *= inv; ny *= inv; nz *= inv;
        if (j == 0) mask = (nx > 0.f) ? 1.f : -1.f;
        nx *= mask; ny *= mask; nz *= mask;
        float pos = (nx*cx + ny*cy + nz*cz) * 0.57735026918962576f; // /sqrt(3)
        float dt = ax*ex + ay*ey + az*ez;
        float nA = sqrtf(ax*ax + ay*ay + az*az);
        float nB = sqrtf(ex*ex + ey*ey + ez*ez);
        float ct = dt / (nA*nB + 1e-8f);
        ct = fminf(1.f, fmaxf(-1.f, ct));
        float ang = acosf(ct);
        float feat[10] = {cx, cy, cz, nx, ny, nz, pos, ang, nA, nB};
        #pragma unroll
        for (int ch = 0; ch < 10; ch++) {
            float h = b1s[ch];
            #pragma unroll
            for (int f = 0; f < 10; f++) h = fmaf(feat[f], w1s[ch*10+f], h);
            g_h1[(size_t)(j*10 + ch) * NPTS + point] = h;  // coalesced store
            s[ch] += h; ss[ch] += h * h;
        }
    }

    // deterministic block reduction of stats
    __syncthreads();  // done reading sp; reuse as reduction buffer
    float* red = (float*)sraw;
    #pragma unroll
    for (int off = 16; off; off >>= 1) {
        #pragma unroll
        for (int ch = 0; ch < 10; ch++) {
            s[ch]  += __shfl_down_sync(0xffffffffu, s[ch],  off);
            ss[ch] += __shfl_down_sync(0xffffffffu, ss[ch], off);
        }
    }
    int wid = tid >> 5, lid = tid & 31;
    if (lid == 0) {
        #pragma unroll
        for (int ch = 0; ch < 10; ch++) {
            red[wid*20 + ch]      = s[ch];
            red[wid*20 + 10 + ch] = ss[ch];
        }
    }
    __syncthreads();
    if (tid < 20) {
        float v = red[tid] + red[20+tid] + red[40+tid] + red[60+tid];
        g_part1[blockIdx.x*20 + tid] = v;
    }
}

// ---------------------------------------------------------------------------
// K2/K4: finalize BN stats -> scale/shift (warp per channel: 20 warps)
// ---------------------------------------------------------------------------
__global__ void kreduce(int which, const float* __restrict__ g,
                        const float* __restrict__ be)
{
    __shared__ float red[20];
    const float* part = which ? g_part2 : g_part1;
    float* bn = which ? g_bn2 : g_bn1;
    int w = threadIdx.x >> 5, l = threadIdx.x & 31;
    if (w < 20) {
        float v = 0.f;
        #pragma unroll
        for (int i = 0; i < NBLK1/32; i++) v += part[(l + i*32)*20 + w];
        #pragma unroll
        for (int off = 16; off; off >>= 1) v += __shfl_down_sync(0xffffffffu, v, off);
        if (l == 0) red[w] = v;
    }
    __syncthreads();
    int t = threadIdx.x;
    if (t < 10) {
        const float inv_n = 1.0f / (float)NROWS;
        float mean = red[t] * inv_n;
        float var  = red[10+t] * inv_n - mean * mean;
        float sc = g[t] * rsqrtf(var + 1e-5f);
        bn[t]      = sc;
        bn[10 + t] = be[t] - mean * sc;
    }
}

// ---------------------------------------------------------------------------
// K3: bn1+relu -> linear2; per-point max/min of h2; partial BN2 stats
// ---------------------------------------------------------------------------
__global__ void __launch_bounds__(TPB1) k3_layer2(
    const float* __restrict__ W2, const float* __restrict__ b2)
{
    __shared__ float w2s[100], b2s[10], sc1[10], sh1[10];
    __shared__ float red[80];
    int tid = threadIdx.x;
    if (tid < 100) w2s[tid] = W2[tid];
    if (tid < 10) {
        b2s[tid] = b2[tid];
        sc1[tid] = g_bn1[tid];
        sh1[tid] = g_bn1[10 + tid];
    }
    __syncthreads();

    int point = blockIdx.x * TPB1 + tid;

    float mx[10], mn[10], s[10], ss[10];
    #pragma unroll
    for (int ch = 0; ch < 10; ch++) {
        mx[ch] = -FLT_MAX; mn[ch] = FLT_MAX; s[ch] = 0.f; ss[ch] = 0.f;
    }
    #pragma unroll 1
    for (int j = 0; j < 9; j++) {
        float t1[10];
        #pragma unroll
        for (int ch = 0; ch < 10; ch++) {
            float h = fmaf(g_h1[(size_t)(j*10 + ch) * NPTS + point], sc1[ch], sh1[ch]);
            t1[ch] = fmaxf(h, 0.f);   // coalesced load
        }
        #pragma unroll
        for (int ch = 0; ch < 10; ch++) {
            float h2 = b2s[ch];
            #pragma unroll
            for (int f = 0; f < 10; f++) h2 = fmaf(t1[f], w2s[ch*10+f], h2);
            mx[ch] = fmaxf(mx[ch], h2);
            mn[ch] = fminf(mn[ch], h2);
            s[ch] += h2; ss[ch] += h2 * h2;
        }
    }
    #pragma unroll
    for (int ch = 0; ch < 10; ch++) {
        g_mm[(size_t)point*20 + ch]      = mx[ch];
        g_mm[(size_t)point*20 + 10 + ch] = mn[ch];
    }

    #pragma unroll
    for (int off = 16; off; off >>= 1) {
        #pragma unroll
        for (int ch = 0; ch < 10; ch++) {
            s[ch]  += __shfl_down_sync(0xffffffffu, s[ch],  off);
            ss[ch] += __shfl_down_sync(0xffffffffu, ss[ch], off);
        }
    }
    int wid = tid >> 5, lid = tid & 31;
    if (lid == 0) {
        #pragma unroll
        for (int ch = 0; ch < 10; ch++) {
            red[wid*20 + ch]      = s[ch];
            red[wid*20 + 10 + ch] = ss[ch];
        }
    }
    __syncthreads();
    if (tid < 20) {
        float v = red[tid] + red[20+tid] + red[40+tid] + red[60+tid];
        g_part2[blockIdx.x*20 + tid] = v;
    }
}

// ---------------------------------------------------------------------------
// K5: out = max_k relu(bn2(h2)) via monotonicity: pick max (a>=0) or min (a<0)
// ---------------------------------------------------------------------------
__global__ void k5_final(float* __restrict__ out)
{
    int i = blockIdx.x * 256 + threadIdx.x;
    if (i >= NPTS * 10) return;
    int point = i / 10, ch = i - point * 10;
    float a = g_bn2[ch], sh = g_bn2[10 + ch];
    float h = (a >= 0.f) ? g_mm[(size_t)point*20 + ch]
                         : g_mm[(size_t)point*20 + 10 + ch];
    out[i] = fmaxf(fmaf(a, h, sh), 0.f);
}

// ---------------------------------------------------------------------------
extern "C" void kernel_launch(void* const* d_in, const int* in_sizes, int n_in,
                              void* d_out, int out_size)
{
    const float* x   = (const float*)d_in[0];
    const float* W1  = (const float*)d_in[1];
    const float* b1  = (const float*)d_in[2];
    const float* g1  = (const float*)d_in[3];
    const float* be1 = (const float*)d_in[4];
    const float* W2  = (const float*)d_in[5];
    const float* b2  = (const float*)d_in[6];
    const float* g2  = (const float*)d_in[7];
    const float* be2 = (const float*)d_in[8];
    float* out = (float*)d_out;

    cudaFuncSetAttribute(k1_knn_feat,
                         cudaFuncAttributeMaxDynamicSharedMemorySize, SMEM1);

    k1_knn_feat<<<NBLK1, TPB1, SMEM1>>>(x, W1, b1);
    kreduce<<<1, 640>>>(0, g1, be1);
    k3_layer2<<<NBLK1, TPB1>>>(W2, b2);
    kreduce<<<1, 640>>>(1, g2, be2);
    k5_final<<<(NPTS*10 + 255)/256, 256>>>(out);
}